// round 16
// baseline (speedup 1.0000x reference)
#include <cuda_runtime.h>
#include <math.h>
#include <stdint.h>

// GAT layer: B=8, N=1024, IN=256, OUT=256 (H=4 heads x D=64)

#define B_ 8
#define N_ 1024
#define K_ 256
#define O_ 256
#define H_ 4
#define D_ 64
#define IDXP_ 1032   // padded row stride for g_idx

__device__ float g_Wh[B_ * N_ * O_];              // 32 MB
__device__ float g_src[B_ * H_ * N_];
__device__ float g_dst[B_ * H_ * N_];
__device__ unsigned short g_idx[B_ * N_ * IDXP_]; // compacted neighbor lists
__device__ int g_cnt[B_ * N_];

// ---------------------------------------------------------------------------
// Kernel A (heterogeneous blocks):
//   even blockIdx  -> GEMM tile: Wh = h @ W^T (+ fused src/dst epilogue)
//                     128x64 tile, 256 threads, 8x4 micro-tile (round-11)
//   odd blockIdx   -> mask compaction: 32 rows/block, warp-per-row x4,
//                     sorted-j indices + count + sentinel pad to global.
// Compaction uses LSU/ALU while gemm blocks saturate the FMA pipe ->
// the mask work rides free under the gemm's ~31us FMA floor.
// ---------------------------------------------------------------------------
__global__ void __launch_bounds__(256) gemm_compact_kernel(
    const float* __restrict__ A, const float* __restrict__ Wt,
    const float* __restrict__ avec, const void* __restrict__ mask)
{
    __shared__ float As[16][128];   // [k][m]
    __shared__ float Bs[16][64];    // [k][o]
    __shared__ int sFlags;

    int tid = threadIdx.x;
    int lane = tid & 31;
    int warp = tid >> 5;
    int bid = blockIdx.x;

    if (bid & 1) {
        // ----- compaction path: rows ci*32 .. ci*32+31 -----
        int ci = bid >> 1;                    // 0..255
        if (tid == 0) sFlags = 0;
        __syncthreads();
        // mask-kind detection from first 4KB (uint4 per thread)
        {
            uint4 v = reinterpret_cast<const uint4*>(mask)[tid];
            bool isF = (v.x == 0x3F800000u) | (v.y == 0x3F800000u) |
                       (v.z == 0x3F800000u) | (v.w == 0x3F800000u);
            bool isB = ((v.x > 1u) & (v.x != 0x3F800000u)) |
                       ((v.y > 1u) & (v.y != 0x3F800000u)) |
                       ((v.z > 1u) & (v.z != 0x3F800000u)) |
                       ((v.w > 1u) & (v.w != 0x3F800000u));
            unsigned bF = __ballot_sync(0xFFFFFFFFu, isF);
            unsigned bB = __ballot_sync(0xFFFFFFFFu, isB);
            if (lane == 0) {
                int f = (bF ? 1 : 0) | (bB ? 2 : 0);
                if (f) atomicOr(&sFlags, f);
            }
        }
        __syncthreads();
        int flags = sFlags;
        int kind = (flags & 1) ? 2 : ((flags & 2) ? 0 : 1);

        #pragma unroll
        for (int rr = 0; rr < 4; ++rr) {
            int row = ci * 32 + warp * 4 + rr;        // b*N+i, 0..8191
            size_t mb = (size_t)row * N_;
            unsigned short* op = g_idx + (size_t)row * IDXP_;
            int off = 0;
            #pragma unroll 4
            for (int it = 0; it < 32; ++it) {
                int j = it * 32 + lane;
                bool val;
                if (kind == 0)      val = ((const unsigned char*)mask)[mb + j] != 0;
                else if (kind == 1) val = ((const int*)mask)[mb + j] != 0;
                else                val = ((const float*)mask)[mb + j] != 0.0f;
                unsigned bal = __ballot_sync(0xFFFFFFFFu, val);
                int pos = off + __popc(bal & ((1u << lane) - 1u));
                if (val) op[pos] = (unsigned short)j;
                off += __popc(bal);
            }
            if (lane == 0) g_cnt[row] = off;
            int pad = (off + 7) & ~7;
            if (lane < pad - off) op[off + lane] = 0;
        }
        return;
    }

    // ----- GEMM path (round-11 exact) -----
    int mb2 = bid >> 1;                     // 0..255
    int m0 = (mb2 & 63) * 128;
    int h  = mb2 >> 6;
    int o0 = h * 64;
    int tx = tid & 15;
    int ty = tid >> 4;

    int arow = tid >> 1;
    int aoff = (tid & 1) * 8;
    int brow = tid & 63;
    int boff = (tid >> 6) * 4;

    float acc[8][4] = {};

    for (int k0 = 0; k0 < K_; k0 += 16) {
        float4 a0 = *reinterpret_cast<const float4*>(A + (size_t)(m0 + arow) * K_ + k0 + aoff);
        float4 a1 = *reinterpret_cast<const float4*>(A + (size_t)(m0 + arow) * K_ + k0 + aoff + 4);
        float4 bv = *reinterpret_cast<const float4*>(Wt + (size_t)(o0 + brow) * K_ + k0 + boff);
        __syncthreads();
        As[aoff + 0][arow] = a0.x; As[aoff + 1][arow] = a0.y;
        As[aoff + 2][arow] = a0.z; As[aoff + 3][arow] = a0.w;
        As[aoff + 4][arow] = a1.x; As[aoff + 5][arow] = a1.y;
        As[aoff + 6][arow] = a1.z; As[aoff + 7][arow] = a1.w;
        Bs[boff + 0][brow] = bv.x; Bs[boff + 1][brow] = bv.y;
        Bs[boff + 2][brow] = bv.z; Bs[boff + 3][brow] = bv.w;
        __syncthreads();

        #pragma unroll
        for (int k = 0; k < 16; ++k) {
            float4 t0 = *reinterpret_cast<const float4*>(&As[k][ty * 8]);
            float4 t1 = *reinterpret_cast<const float4*>(&As[k][ty * 8 + 4]);
            float av[8] = {t0.x, t0.y, t0.z, t0.w, t1.x, t1.y, t1.z, t1.w};
            float bv4[4];
            #pragma unroll
            for (int c = 0; c < 4; ++c) bv4[c] = Bs[k][tx + 16 * c];
            #pragma unroll
            for (int i = 0; i < 8; ++i)
                #pragma unroll
                for (int c = 0; c < 4; ++c)
                    acc[i][c] = fmaf(av[i], bv4[c], acc[i][c]);
        }
    }

    #pragma unroll
    for (int i = 0; i < 8; ++i) {
        float* dst = g_Wh + (size_t)(m0 + ty * 8 + i) * O_ + o0 + tx;
        #pragma unroll
        for (int c = 0; c < 4; ++c) dst[16 * c] = acc[i][c];
    }

    float asv[4], adv[4];
    #pragma unroll
    for (int c = 0; c < 4; ++c) {
        asv[c] = __ldg(avec + h * (2 * D_) + tx + 16 * c);
        adv[c] = __ldg(avec + h * (2 * D_) + D_ + tx + 16 * c);
    }
    int b = m0 >> 10;
    int nbase = (m0 & (N_ - 1)) + ty * 8;
    #pragma unroll
    for (int i = 0; i < 8; ++i) {
        float s = 0.f, t = 0.f;
        #pragma unroll
        for (int c = 0; c < 4; ++c) {
            s = fmaf(acc[i][c], asv[c], s);
            t = fmaf(acc[i][c], adv[c], t);
        }
        #pragma unroll
        for (int off = 8; off; off >>= 1) {
            s += __shfl_xor_sync(0xFFFFFFFFu, s, off);
            t += __shfl_xor_sync(0xFFFFFFFFu, t, off);
        }
        if (tx == 0) {
            g_src[(b * H_ + h) * N_ + nbase + i] = s;
            g_dst[(b * H_ + h) * N_ + nbase + i] = t;
        }
    }
}

// ---------------------------------------------------------------------------
// Kernel B: attention — round-11 hot path EXACTLY (measured 59.7us), with
// compaction pre-done: reads g_cnt + coalesced g_idx, no mask work, no
// detection, no scan, 3 fewer barriers.
// ---------------------------------------------------------------------------
__global__ void __launch_bounds__(256, 8) attn_kernel(float* __restrict__ out)
{
    __shared__ __align__(16) unsigned sh_pk[H_][N_ + 8];   // packed (p|j)
    __shared__ float sred[H_][2];
    __shared__ float sacc[8][64];

    int tid = threadIdx.x;
    int bid = blockIdx.x;                      // b*N + i
    int i = bid & (N_ - 1);
    int b = bid >> 10;
    int lane = tid & 31;
    int warp = tid >> 5;

    int cnt = __ldg(&g_cnt[bid]);
    int pad = (cnt + 7) & ~7;

    int h   = tid >> 6;
    int l64 = tid & 63;
    int wig = (tid >> 5) & 1;

    const unsigned short* idxp = g_idx + (size_t)bid * IDXP_;
    const float* dstv = g_dst + (size_t)(b * H_ + h) * N_;
    float srci = __ldg(g_src + (size_t)(b * H_ + h) * N_ + i);

    // phase 1: e -> p -> packed (p-hi-bits | j), sum (sentinels get p=0)
    float lsum = 0.f;
    for (int k = l64; k < pad; k += 64) {
        unsigned j = __ldg(idxp + k);
        unsigned pb = 0;
        if (k < cnt) {
            float x = srci + dstv[j];
            float e = x > 0.f ? x : 0.2f * x;
            float p = __expf(e);
            pb = (__float_as_uint(p) & ~1023u) | j;
        }
        sh_pk[h][k] = pb;
        lsum += __uint_as_float(pb & ~1023u);
    }
    #pragma unroll
    for (int off = 16; off; off >>= 1)
        lsum += __shfl_xor_sync(0xFFFFFFFFu, lsum, off);
    if (lane == 0) sred[h][wig] = lsum;
    __syncthreads();

    // phase 2: warp = (head, k-parity over quads). Lane owns a d-pair.
    {
        int hh   = warp >> 1;
        int half = warp & 1;
        const float2* whb = reinterpret_cast<const float2*>(
            g_Wh + (size_t)b * N_ * O_ + hh * D_) + lane;
        const uint4* pk4 = reinterpret_cast<const uint4*>(sh_pk[hh]);
        float ax = 0.f, ay = 0.f;
        int nq = pad >> 2;
        for (int q = half; q < nq; q += 2) {
            uint4 pb = pk4[q];
            float2 w0 = whb[(size_t)(pb.x & 1023u) * 128];
            float2 w1 = whb[(size_t)(pb.y & 1023u) * 128];
            float2 w2 = whb[(size_t)(pb.z & 1023u) * 128];
            float2 w3 = whb[(size_t)(pb.w & 1023u) * 128];
            float p0 = __uint_as_float(pb.x & ~1023u);
            float p1 = __uint_as_float(pb.y & ~1023u);
            float p2 = __uint_as_float(pb.z & ~1023u);
            float p3 = __uint_as_float(pb.w & ~1023u);
            ax = fmaf(p0, w0.x, ax);
            ay = fmaf(p0, w0.y, ay);
            ax = fmaf(p1, w1.x, ax);
            ay = fmaf(p1, w1.y, ay);
            ax = fmaf(p2, w2.x, ax);
            ay = fmaf(p2, w2.y, ay);
            ax = fmaf(p3, w3.x, ax);
            ay = fmaf(p3, w3.y, ay);
        }
        sacc[warp][lane * 2]     = ax;
        sacc[warp][lane * 2 + 1] = ay;
    }
    __syncthreads();

    // combine halves + scale + coalesced store
    {
        int hh = tid >> 6;
        int d  = tid & 63;
        float ssum = sred[hh][0] + sred[hh][1];
        float inv = (ssum > 0.f) ? (1.0f / ssum) : 0.f;
        float v = (sacc[2 * hh][d] + sacc[2 * hh + 1][d]) * inv;
        out[(size_t)bid * O_ + hh * D_ + d] = v;
    }
}

// ---------------------------------------------------------------------------
extern "C" void kernel_launch(void* const* d_in, const int* in_sizes, int n_in,
                              void* d_out, int out_size) {
    const float* h = nullptr;
    const float* W = nullptr;
    const float* a = nullptr;
    const void*  mask = nullptr;

    for (int idx = 0; idx < n_in; ++idx) {
        switch (in_sizes[idx]) {
            case B_ * N_ * K_: h    = (const float*)d_in[idx]; break;
            case K_ * O_:      W    = (const float*)d_in[idx]; break;
            case H_ * 2 * D_:  a    = (const float*)d_in[idx]; break;
            case B_ * N_ * N_: mask = d_in[idx];               break;
        }
    }
    if (!h)    h    = (const float*)d_in[0];
    if (!W)    W    = (const float*)d_in[1];
    if (!a)    a    = (const float*)d_in[2];
    if (!mask) mask = d_in[3];

    gemm_compact_kernel<<<512, 256>>>(h, W, a, mask);
    attn_kernel<<<B_ * N_, 256>>>((float*)d_out);
}

// round 17
// speedup vs baseline: 1.1524x; 1.1524x over previous
#include <cuda_runtime.h>
#include <math.h>
#include <stdint.h>

// GAT layer: B=8, N=1024, IN=256, OUT=256 (H=4 heads x D=64)

#define B_ 8
#define N_ 1024
#define K_ 256
#define O_ 256
#define H_ 4
#define D_ 64

__device__ float g_Wh[B_ * N_ * O_];      // [b*N+n][o]  (o = h*64+d), 32 MB
__device__ float g_src[B_ * H_ * N_];
__device__ float g_dst[B_ * H_ * N_];

// ---------------------------------------------------------------------------
// Kernel A: Wh = h @ W^T with fused src/dst epilogue (round-11 exact).
// 128x64 tile (o-block = one head), 256 threads, 8x4 micro-tile.
// ---------------------------------------------------------------------------
__global__ void __launch_bounds__(256) gemm_kernel(
    const float* __restrict__ A, const float* __restrict__ Wt,
    const float* __restrict__ avec)
{
    __shared__ float As[16][128];   // [k][m]
    __shared__ float Bs[16][64];    // [k][o]

    int tid = threadIdx.x;
    int tx = tid & 15;
    int ty = tid >> 4;
    int m0 = blockIdx.x * 128;
    int h  = blockIdx.y;
    int o0 = h * 64;

    int arow = tid >> 1;
    int aoff = (tid & 1) * 8;
    int brow = tid & 63;
    int boff = (tid >> 6) * 4;

    float acc[8][4] = {};

    for (int k0 = 0; k0 < K_; k0 += 16) {
        float4 a0 = *reinterpret_cast<const float4*>(A + (size_t)(m0 + arow) * K_ + k0 + aoff);
        float4 a1 = *reinterpret_cast<const float4*>(A + (size_t)(m0 + arow) * K_ + k0 + aoff + 4);
        float4 bv = *reinterpret_cast<const float4*>(Wt + (size_t)(o0 + brow) * K_ + k0 + boff);
        __syncthreads();
        As[aoff + 0][arow] = a0.x; As[aoff + 1][arow] = a0.y;
        As[aoff + 2][arow] = a0.z; As[aoff + 3][arow] = a0.w;
        As[aoff + 4][arow] = a1.x; As[aoff + 5][arow] = a1.y;
        As[aoff + 6][arow] = a1.z; As[aoff + 7][arow] = a1.w;
        Bs[boff + 0][brow] = bv.x; Bs[boff + 1][brow] = bv.y;
        Bs[boff + 2][brow] = bv.z; Bs[boff + 3][brow] = bv.w;
        __syncthreads();

        #pragma unroll
        for (int k = 0; k < 16; ++k) {
            float4 t0 = *reinterpret_cast<const float4*>(&As[k][ty * 8]);
            float4 t1 = *reinterpret_cast<const float4*>(&As[k][ty * 8 + 4]);
            float av[8] = {t0.x, t0.y, t0.z, t0.w, t1.x, t1.y, t1.z, t1.w};
            float bv4[4];
            #pragma unroll
            for (int c = 0; c < 4; ++c) bv4[c] = Bs[k][tx + 16 * c];
            #pragma unroll
            for (int i = 0; i < 8; ++i)
                #pragma unroll
                for (int c = 0; c < 4; ++c)
                    acc[i][c] = fmaf(av[i], bv4[c], acc[i][c]);
        }
    }

    #pragma unroll
    for (int i = 0; i < 8; ++i) {
        float* dst = g_Wh + (size_t)(m0 + ty * 8 + i) * O_ + o0 + tx;
        #pragma unroll
        for (int c = 0; c < 4; ++c) dst[16 * c] = acc[i][c];
    }

    float asv[4], adv[4];
    #pragma unroll
    for (int c = 0; c < 4; ++c) {
        asv[c] = __ldg(avec + h * (2 * D_) + tx + 16 * c);
        adv[c] = __ldg(avec + h * (2 * D_) + D_ + tx + 16 * c);
    }
    int b = m0 >> 10;
    int nbase = (m0 & (N_ - 1)) + ty * 8;
    #pragma unroll
    for (int i = 0; i < 8; ++i) {
        float s = 0.f, t = 0.f;
        #pragma unroll
        for (int c = 0; c < 4; ++c) {
            s = fmaf(acc[i][c], asv[c], s);
            t = fmaf(acc[i][c], adv[c], t);
        }
        #pragma unroll
        for (int off = 8; off; off >>= 1) {
            s += __shfl_xor_sync(0xFFFFFFFFu, s, off);
            t += __shfl_xor_sync(0xFFFFFFFFu, t, off);
        }
        if (tx == 0) {
            g_src[(b * H_ + h) * N_ + nbase + i] = s;
            g_dst[(b * H_ + h) * N_ + nbase + i] = t;
        }
    }
}

// ---------------------------------------------------------------------------
// Kernel B: attention — round-11 structure; phase 2 reworked to serve TWO
// neighbors per LDG.128 (lanes 0-15 -> n0's 64-float row as float4,
// lanes 16-31 -> n1's). Same wavefront traffic, ~35% fewer instructions in
// the dominant loop. shfl_xor(16) merges even/odd-neighbor partials
// (fixed order -> deterministic).
// ---------------------------------------------------------------------------
__global__ void __launch_bounds__(256, 8) attn_kernel(
    const void* __restrict__ mask, float* __restrict__ out)
{
    __shared__ unsigned short sh_idx[N_ + 8];
    __shared__ __align__(16) unsigned sh_pk[H_][N_ + 8];
    __shared__ int   sWc[32];
    __shared__ int   sOff[32];
    __shared__ int   sCnt;
    __shared__ int   sFlags;
    __shared__ float sred[H_][2];
    __shared__ __align__(16) float sacc[8][64];

    int tid = threadIdx.x;
    int bid = blockIdx.x;                      // b*N + i
    int i = bid & (N_ - 1);
    int b = bid >> 10;
    int lane = tid & 31;
    int warp = tid >> 5;

    if (tid == 0) sFlags = 0;
    __syncthreads();

    // mask-kind detection from first 4KB (uint4 per thread, L2 broadcast)
    {
        uint4 v = reinterpret_cast<const uint4*>(mask)[tid];
        bool isF = (v.x == 0x3F800000u) | (v.y == 0x3F800000u) |
                   (v.z == 0x3F800000u) | (v.w == 0x3F800000u);
        bool isB = ((v.x > 1u) & (v.x != 0x3F800000u)) |
                   ((v.y > 1u) & (v.y != 0x3F800000u)) |
                   ((v.z > 1u) & (v.z != 0x3F800000u)) |
                   ((v.w > 1u) & (v.w != 0x3F800000u));
        unsigned bF = __ballot_sync(0xFFFFFFFFu, isF);
        unsigned bB = __ballot_sync(0xFFFFFFFFu, isB);
        if (lane == 0) {
            int f = (bF ? 1 : 0) | (bB ? 2 : 0);
            if (f) atomicOr(&sFlags, f);
        }
    }
    __syncthreads();
    int flags = sFlags;
    int kind = (flags & 1) ? 2 : ((flags & 2) ? 0 : 1);

    size_t mbase = ((size_t)b * N_ + i) * N_;

    // phase 0a: batched mask loads, then ballots
    bool vv[4];
    #pragma unroll
    for (int r = 0; r < 4; ++r) {
        int j = r * 256 + warp * 32 + lane;
        if (kind == 0)      vv[r] = ((const unsigned char*)mask)[mbase + j] != 0;
        else if (kind == 1) vv[r] = ((const int*)mask)[mbase + j] != 0;
        else                vv[r] = ((const float*)mask)[mbase + j] != 0.0f;
    }
    unsigned bal[4];
    #pragma unroll
    for (int r = 0; r < 4; ++r)
        bal[r] = __ballot_sync(0xFFFFFFFFu, vv[r]);
    if (lane == 0) {
        sWc[0 * 8 + warp] = __popc(bal[0]);
        sWc[1 * 8 + warp] = __popc(bal[1]);
        sWc[2 * 8 + warp] = __popc(bal[2]);
        sWc[3 * 8 + warp] = __popc(bal[3]);
    }
    __syncthreads();

    // phase 0b: exclusive scan over the 32 counts (warp 0)
    if (warp == 0) {
        int c = sWc[lane];
        int x = c;
        #pragma unroll
        for (int off = 1; off < 32; off <<= 1) {
            int y = __shfl_up_sync(0xFFFFFFFFu, x, off);
            if (lane >= off) x += y;
        }
        sOff[lane] = x - c;
        if (lane == 31) sCnt = x;
    }
    __syncthreads();
    int cnt = sCnt;
    int pad = (cnt + 7) & ~7;

    // phase 0c: indexed writes (sorted j order) + sentinel padding
    #pragma unroll
    for (int r = 0; r < 4; ++r) {
        if ((bal[r] >> lane) & 1u) {
            int pos = sOff[r * 8 + warp] + __popc(bal[r] & ((1u << lane) - 1u));
            sh_idx[pos] = (unsigned short)(r * 256 + warp * 32 + lane);
        }
    }
    if (tid < pad - cnt) sh_idx[cnt + tid] = 0;
    __syncthreads();

    int h   = tid >> 6;
    int l64 = tid & 63;
    int wig = (tid >> 5) & 1;

    const float* dstv = g_dst + (size_t)(b * H_ + h) * N_;
    float srci = __ldg(g_src + (size_t)(b * H_ + h) * N_ + i);

    // phase 1: e -> p -> packed (p-hi-bits | j), sum (sentinels get p=0)
    float lsum = 0.f;
    for (int k = l64; k < pad; k += 64) {
        unsigned j = sh_idx[k];
        unsigned pb = 0;
        if (k < cnt) {
            float x = srci + dstv[j];
            float e = x > 0.f ? x : 0.2f * x;
            float p = __expf(e);
            pb = (__float_as_uint(p) & ~1023u) | j;
        }
        sh_pk[h][k] = pb;
        lsum += __uint_as_float(pb & ~1023u);
    }
    #pragma unroll
    for (int off = 16; off; off >>= 1)
        lsum += __shfl_xor_sync(0xFFFFFFFFu, lsum, off);
    if (lane == 0) sred[h][wig] = lsum;
    __syncthreads();

    // phase 2: warp = (head, k-parity over quads). Half-warp = neighbor
    // parity within the quad; lane owns 4 d-values (float4).
    {
        int hh   = warp >> 1;
        int half = warp & 1;
        bool hiH = lane >= 16;
        const char* whbase = reinterpret_cast<const char*>(
            g_Wh + (size_t)b * N_ * O_ + hh * D_) + (lane & 15) * 16;
        const uint4* pk4 = reinterpret_cast<const uint4*>(sh_pk[hh]);
        float4 acc = make_float4(0.f, 0.f, 0.f, 0.f);
        int nq = pad >> 2;
        for (int q = half; q < nq; q += 2) {
            uint4 pb = pk4[q];
            unsigned s0 = hiH ? pb.y : pb.x;
            unsigned s1 = hiH ? pb.w : pb.z;
            float4 w0 = *reinterpret_cast<const float4*>(
                whbase + (size_t)(s0 & 1023u) * 1024);
            float4 w1 = *reinterpret_cast<const float4*>(
                whbase + (size_t)(s1 & 1023u) * 1024);
            float p0 = __uint_as_float(s0 & ~1023u);
            float p1 = __uint_as_float(s1 & ~1023u);
            acc.x = fmaf(p0, w0.x, acc.x);
            acc.y = fmaf(p0, w0.y, acc.y);
            acc.z = fmaf(p0, w0.z, acc.z);
            acc.w = fmaf(p0, w0.w, acc.w);
            acc.x = fmaf(p1, w1.x, acc.x);
            acc.y = fmaf(p1, w1.y, acc.y);
            acc.z = fmaf(p1, w1.z, acc.z);
            acc.w = fmaf(p1, w1.w, acc.w);
        }
        // merge even/odd-neighbor partials across half-warps
        acc.x += __shfl_xor_sync(0xFFFFFFFFu, acc.x, 16);
        acc.y += __shfl_xor_sync(0xFFFFFFFFu, acc.y, 16);
        acc.z += __shfl_xor_sync(0xFFFFFFFFu, acc.z, 16);
        acc.w += __shfl_xor_sync(0xFFFFFFFFu, acc.w, 16);
        if (!hiH)
            *reinterpret_cast<float4*>(&sacc[warp][(lane & 15) * 4]) = acc;
    }
    __syncthreads();

    // combine halves + scale + coalesced store
    {
        int hh = tid >> 6;
        int d  = tid & 63;
        float ssum = sred[hh][0] + sred[hh][1];
        float inv = (ssum > 0.f) ? (1.0f / ssum) : 0.f;
        float v = (sacc[2 * hh][d] + sacc[2 * hh + 1][d]) * inv;
        out[(size_t)bid * O_ + hh * D_ + d] = v;
    }
}

// ---------------------------------------------------------------------------
extern "C" void kernel_launch(void* const* d_in, const int* in_sizes, int n_in,
                              void* d_out, int out_size) {
    const float* h = nullptr;
    const float* W = nullptr;
    const float* a = nullptr;
    const void*  mask = nullptr;

    for (int idx = 0; idx < n_in; ++idx) {
        switch (in_sizes[idx]) {
            case B_ * N_ * K_: h    = (const float*)d_in[idx]; break;
            case K_ * O_:      W    = (const float*)d_in[idx]; break;
            case H_ * 2 * D_:  a    = (const float*)d_in[idx]; break;
            case B_ * N_ * N_: mask = d_in[idx];               break;
        }
    }
    if (!h)    h    = (const float*)d_in[0];
    if (!W)    W    = (const float*)d_in[1];
    if (!a)    a    = (const float*)d_in[2];
    if (!mask) mask = d_in[3];

    gemm_kernel<<<dim3((B_ * N_) / 128, H_), 256>>>(h, W, a);
    attn_kernel<<<B_ * N_, 256>>>(mask, (float*)d_out);
}